// round 14
// baseline (speedup 1.0000x reference)
#include <cuda_runtime.h>
#include <math.h>

#define NN   50000
#define EE   1600000
#define ETOT (EE + NN)   // edges + self-loops
#define GG   512
#define HC   32          // H*C

// ---------------- scratch (device globals) ----------------------------------
__device__ __align__(16) float g_deg  [NN];
__device__ __align__(16) float g_xl   [NN * HC];
__device__ __align__(16) float g_xr   [NN * HC];
__device__ __align__(16) float g_out  [NN * HC];
__device__ __align__(16) float g_denom[NN * 2];
__device__ __align__(16) float g_sums [GG * HC];
__device__ __align__(16) float g_cnt  [GG];

static inline int div_up(int a, int b) { return (a + b - 1) / b; }

__device__ __forceinline__ void red4(float* p, float4 v) {
    asm volatile("red.global.add.v4.f32 [%0], {%1,%2,%3,%4};"
                 :: "l"(p), "f"(v.x), "f"(v.y), "f"(v.z), "f"(v.w) : "memory");
}

// ---------------- prep -------------------------------------------------------

// zero degree + pool accumulators (one pass)
__global__ void k_zeroall() {
    int i = blockIdx.x * blockDim.x + threadIdx.x;
    if (i < NN) g_deg[i] = 0.f;
    if (i < GG * HC) g_sums[i] = 0.f;
    if (i < GG) g_cnt[i] = 0.f;
}

__global__ void k_degree(const int* __restrict__ ei) {
    int e = blockIdx.x * blockDim.x + threadIdx.x;
    if (e < EE) {
        atomicAdd(&g_deg[ei[e]], 1.f);
        atomicAdd(&g_deg[ei[EE + e]], 1.f);
    }
}

// conv1 linear with features [1, deg, rand] built inline; zeroes out/denom;
// also accumulates per-graph node counts (needed only by k_head at the end).
__global__ void k_lin3(const float* __restrict__ rf, const int* __restrict__ batch,
                       const float* __restrict__ Wl, const float* __restrict__ bl,
                       const float* __restrict__ Wr, const float* __restrict__ br) {
    int t = blockIdx.x * blockDim.x + threadIdx.x;
    if (t >= NN * HC) return;
    int n = t >> 5, o = t & 31;
    float x1 = g_deg[n], x2 = rf[n];
    g_xl[t] = bl[o] + Wl[o * 3] + Wl[o * 3 + 1] * x1 + Wl[o * 3 + 2] * x2;
    g_xr[t] = br[o] + Wr[o * 3] + Wr[o * 3 + 1] * x1 + Wr[o * 3 + 2] * x2;
    g_out[t] = 0.f;
    if (o < 2) g_denom[n * 2 + o] = 0.f;
    if (o == 0) atomicAdd(&g_cnt[batch[n]], 1.f);
}

// ---------------- fused conv edge pass (unchanged: measured 63us, L1-bound) --
// 4 edges per warp, 8 lanes per edge (float4 of channels each).
// score -> clamp(+-60) -> exp -> unnormalized aggregate + denom.
// Softmax shift-invariance makes this identical to the max-subtracted form.
__global__ void k_conv_fused(const int* __restrict__ ei, const float* __restrict__ att) {
    int t = blockIdx.x * blockDim.x + threadIdx.x;
    int e = t >> 3;
    if (e >= ETOT) return;
    int j = t & 7;
    int s, d;
    if (e < EE) { s = ei[e]; d = ei[EE + e]; }
    else        { s = d = e - EE; }
    const float4* xl4 = (const float4*)g_xl;
    const float4* xr4 = (const float4*)g_xr;
    float4 a = xl4[s * 8 + j];
    float4 b = xr4[d * 8 + j];
    float4 w = ((const float4*)att)[j];
    float m0 = a.x + b.x, m1 = a.y + b.y, m2 = a.z + b.z, m3 = a.w + b.w;
    m0 = fmaxf(m0, 0.2f * m0);   // LeakyReLU(0.2)
    m1 = fmaxf(m1, 0.2f * m1);
    m2 = fmaxf(m2, 0.2f * m2);
    m3 = fmaxf(m3, 0.2f * m3);
    float v = m0 * w.x + m1 * w.y + m2 * w.z + m3 * w.w;
    v += __shfl_xor_sync(0xffffffffu, v, 1);
    v += __shfl_xor_sync(0xffffffffu, v, 2);   // lanes 0-3: head0, 4-7: head1
    v = fminf(fmaxf(v, -60.f), 60.f);
    float ex = __expf(v);
    red4(&g_out[d * HC + 4 * j],
         make_float4(a.x * ex, a.y * ex, a.z * ex, a.w * ex));
    if ((j & 3) == 0)
        atomicAdd(&g_denom[d * 2 + (j >> 2)], ex);
}

// ---------------- conv1 epilogue fused with conv2 linear ---------------------
// warp = node, lane = channel.  v = ELU(out/denom + bias) lives in registers;
// 32x32 matvec via shuffle broadcast writes xl/xr for conv2 directly.
// Also re-zeroes g_out/g_denom for conv2.
__global__ void k_fin_lin32(const float* __restrict__ bias,
                            const float* __restrict__ Wl, const float* __restrict__ bl,
                            const float* __restrict__ Wr, const float* __restrict__ br) {
    int t = blockIdx.x * blockDim.x + threadIdx.x;
    if (t >= NN * HC) return;
    int n = t >> 5, o = t & 31, h = o >> 4;
    float den = g_denom[n * 2 + h];
    float v = g_out[t] / (den + 1e-16f) + bias[o];
    v = (v > 0.f) ? v : expm1f(v);
    __syncwarp();
    g_out[t] = 0.f;
    if (o < 2) g_denom[n * 2 + o] = 0.f;
    float al = bl[o], ar = br[o];
#pragma unroll
    for (int k = 0; k < 32; k++) {
        float xk = __shfl_sync(0xffffffffu, v, k);
        al += Wl[o * 32 + k] * xk;
        ar += Wr[o * 32 + k] * xk;
    }
    g_xl[t] = al;
    g_xr[t] = ar;
}

// ---------------- conv2 epilogue fused with mean-pool ------------------------
// warp = node.  v = ELU(out/denom + bias); shuffle-pack 4 channels per lane,
// lanes 0-7 issue one red.v4 each into g_sums[batch[n]].
__global__ void k_fin_pool(const float* __restrict__ bias,
                           const int* __restrict__ batch) {
    const unsigned FULL = 0xffffffffu;
    int t = blockIdx.x * blockDim.x + threadIdx.x;
    if (t >= NN * HC) return;
    int n = t >> 5, o = t & 31, h = o >> 4;
    float den = g_denom[n * 2 + h];
    float v = g_out[t] / (den + 1e-16f) + bias[o];
    v = (v > 0.f) ? v : expm1f(v);
    int base = (o & 7) * 4;
    float a0 = __shfl_sync(FULL, v, base + 0);
    float a1 = __shfl_sync(FULL, v, base + 1);
    float a2 = __shfl_sync(FULL, v, base + 2);
    float a3 = __shfl_sync(FULL, v, base + 3);
    if (o < 8) {
        int g = batch[n];
        red4(&g_sums[g * HC + 4 * o], make_float4(a0, a1, a2, a3));
    }
}

__global__ void k_head(const float* __restrict__ Wfc, const float* __restrict__ bfc,
                       float* __restrict__ out) {
    int g = blockIdx.x * blockDim.x + threadIdx.x;
    if (g >= GG) return;
    float inv = 1.f / fmaxf(g_cnt[g], 1.f);
    float l0 = bfc[0], l1 = bfc[1];
#pragma unroll
    for (int k = 0; k < HC; k++) {
        float p = g_sums[g * HC + k] * inv;
        l0 += Wfc[k] * p;
        l1 += Wfc[HC + k] * p;
    }
    float mx  = fmaxf(l0, l1);
    float lse = mx + logf(expf(l0 - mx) + expf(l1 - mx));
    out[g * 2 + 0] = l0 - lse;
    out[g * 2 + 1] = l1 - lse;
}

// ---------------- launch -----------------------------------------------------

extern "C" void kernel_launch(void* const* d_in, const int* in_sizes, int n_in,
                              void* d_out, int out_size) {
    const int* ei    = (const int*)d_in[0];
    const int* batch = (const int*)d_in[1];
    const float* rand_feat = (const float*)d_in[2];
    const float* W1l = (const float*)d_in[3];
    const float* b1l = (const float*)d_in[4];
    const float* W1r = (const float*)d_in[5];
    const float* b1r = (const float*)d_in[6];
    const float* att1 = (const float*)d_in[7];
    const float* bias1 = (const float*)d_in[8];
    const float* W2l = (const float*)d_in[9];
    const float* b2l = (const float*)d_in[10];
    const float* W2r = (const float*)d_in[11];
    const float* b2r = (const float*)d_in[12];
    const float* att2 = (const float*)d_in[13];
    const float* bias2 = (const float*)d_in[14];
    const float* Wfc = (const float*)d_in[15];
    const float* bfc = (const float*)d_in[16];
    float* out = (float*)d_out;

    const int B = 256;
    const int gNode   = div_up(NN, B);
    const int gEdge   = div_up(EE, B);
    const int gNodeHC = div_up(NN * HC, B);
    const int gEdge8  = div_up(ETOT * 8, B);

    k_zeroall<<<gNode, B>>>();                                        // 0
    k_degree<<<gEdge, B>>>(ei);                                       // 1
    k_lin3<<<gNodeHC, B>>>(rand_feat, batch, W1l, b1l, W1r, b1r);     // 2

    // ---- conv1 ----
    k_conv_fused<<<gEdge8, B>>>(ei, att1);                            // 3 <- profiled
    k_fin_lin32<<<gNodeHC, B>>>(bias1, W2l, b2l, W2r, b2r);           // 4

    // ---- conv2 ----
    k_conv_fused<<<gEdge8, B>>>(ei, att2);                            // 5
    k_fin_pool<<<gNodeHC, B>>>(bias2, batch);                         // 6

    // ---- head ----
    k_head<<<div_up(GG, B), B>>>(Wfc, bfc, out);                      // 7
}